// round 16
// baseline (speedup 1.0000x reference)
#include <cuda_runtime.h>
#include <math.h>

#define AMAX   76725
#define NCLS   80
#define KTOP   1000
#define NCAND  2048
#define NWORDS 16
#define NBINS  8192
#define THR_SEL 0.98f

#define DEC_THREADS 320
#define DEC_BLOCKS  ((AMAX + DEC_THREADS - 1) / DEC_THREADS)   // 240
#define SEL_BLOCKS  1184

#define MASK_BLOCKS 7        // per class; 80*7=560 blocks ~= 1 wave @4/SM
#define NITEMS      8680     // flattened upper-triangle (wb,i) items per class

__device__ float4              g_boxes[AMAX];
__device__ unsigned long long  g_cand[NCLS * NCAND];
__device__ int                 g_cnt[NCLS];                    // zeroed at end of scan
__device__ float               g_scoreK[NCLS * KTOP];
__device__ float4              g_boxK[NCLS * KTOP];
__device__ float               g_areaK[NCLS * KTOP];
__device__ unsigned long long  g_alive[NCLS * NWORDS];
__device__ unsigned long long  g_mask[NCLS * KTOP * NWORDS];   // words wb<i>>6 never written/read
__device__ unsigned long long  g_rowNZ[NCLS * NWORDS];         // bit i: row i has a nonzero word

// ---------------------------------------------------------------------------
__device__ __forceinline__ unsigned fkey(float s) {
    unsigned b = __float_as_uint(s);
    return (b & 0x80000000u) ? ~b : (b | 0x80000000u);
}
__device__ __forceinline__ float fkey_inv(unsigned k) {
    return __uint_as_float((k & 0x80000000u) ? (k & 0x7FFFFFFFu) : ~k);
}
__device__ __forceinline__ unsigned long long mkkey(float s, unsigned a) {
    return ((unsigned long long)fkey(s) << 32) |
           (unsigned long long)(0xFFFFFFFFu - a);
}

// ---------------------------------------------------------------------------
// Kernel 1: fused decode (blocks [0, DEC_BLOCKS)) + select (rest).
// ---------------------------------------------------------------------------
__global__ __launch_bounds__(DEC_THREADS)
void decode_select_kernel(const float* __restrict__ reg,
                          const float* __restrict__ anch,
                          const float* __restrict__ cls,
                          int A, int C, float W, float H, int astep) {
    if (blockIdx.x < DEC_BLOCKS) {
        int a = blockIdx.x * DEC_THREADS + threadIdx.x;
        if (a >= A) return;
        float4 an = reinterpret_cast<const float4*>(anch)[a];
        float4 dl = reinterpret_cast<const float4*>(reg)[a];
        float aw = an.z - an.x;
        float ah = an.w - an.y;
        float cx = an.x + 0.5f * aw;
        float cy = an.y + 0.5f * ah;
        float pcx = cx + dl.x * 0.1f * aw;
        float pcy = cy + dl.y * 0.1f * ah;
        float pw = expf(dl.z * 0.2f) * aw;
        float ph = expf(dl.w * 0.2f) * ah;
        float4 b;
        b.x = fmaxf(pcx - 0.5f * pw, 0.0f);
        b.y = fmaxf(pcy - 0.5f * ph, 0.0f);
        b.z = fminf(pcx + 0.5f * pw, W);
        b.w = fminf(pcy + 0.5f * ph, H);
        g_boxes[a] = b;
        return;
    }
    // ---- select part ----
    int gthreads = SEL_BLOCKS * DEC_THREADS;
    int t = (blockIdx.x - DEC_BLOCKS) * DEC_THREADS + threadIdx.x;
    int nf4 = (A * C) >> 2;
    const float4* cls4 = reinterpret_cast<const float4*>(cls);
    int e0 = t << 2;
    int a  = e0 / C;
    int c0 = e0 - a * C;      // constant per thread across iterations
    for (int f = t; f < nf4; f += gthreads, a += astep) {
        float4 v = cls4[f];
        if (v.x > THR_SEL) {
            int p = atomicAdd(&g_cnt[c0 + 0], 1);
            if (p < NCAND) g_cand[(c0 + 0) * NCAND + p] = mkkey(v.x, (unsigned)a);
        }
        if (v.y > THR_SEL) {
            int p = atomicAdd(&g_cnt[c0 + 1], 1);
            if (p < NCAND) g_cand[(c0 + 1) * NCAND + p] = mkkey(v.y, (unsigned)a);
        }
        if (v.z > THR_SEL) {
            int p = atomicAdd(&g_cnt[c0 + 2], 1);
            if (p < NCAND) g_cand[(c0 + 2) * NCAND + p] = mkkey(v.z, (unsigned)a);
        }
        if (v.w > THR_SEL) {
            int p = atomicAdd(&g_cnt[c0 + 3], 1);
            if (p < NCAND) g_cand[(c0 + 3) * NCAND + p] = mkkey(v.w, (unsigned)a);
        }
    }
}

// ---------------------------------------------------------------------------
// Kernel 2: per-class sort (+embedded exact-reselect guard), extract top-K.
// ---------------------------------------------------------------------------
__global__ __launch_bounds__(1024)
void sort_kernel(const float* __restrict__ cls, int A, int C) {
    __shared__ unsigned long long buf[4096];       // 32 KB: cand = buf[0..2047]
    __shared__ unsigned long long salive[NWORDS];
    __shared__ int sT, sCnt;
    unsigned long long* cand = buf;
    unsigned*           hist = (unsigned*)buf;

    int c = blockIdx.x, tid = threadIdx.x;
    int n = g_cnt[c];
    bool bad = (n < KTOP) | (n > NCAND);

    if (!bad) {
        for (int i = tid; i < NCAND; i += 1024)
            cand[i] = (i < n) ? g_cand[c * NCAND + i] : 0ull;
        __syncthreads();
    } else {
        for (int i = tid; i < NBINS; i += 1024) hist[i] = 0u;
        if (tid == 0) sCnt = 0;
        __syncthreads();
        for (int a = tid; a < A; a += 1024) {
            float s = cls[a * C + c];
            int b = (int)(s * (float)NBINS);
            b = max(0, min(NBINS - 1, b));
            atomicAdd(&hist[b], 1u);
        }
        __syncthreads();
        if (tid == 0) {
            int cum = 0, t;
            for (t = NBINS - 1; t >= 0; t--) {
                cum += (int)hist[t];
                if (cum >= KTOP) break;
            }
            sT = (t < 0) ? 0 : t;
        }
        __syncthreads();
        int T = sT;
        unsigned long long keys[8]; int nk = 0;
        for (int a = tid; a < A; a += 1024) {
            float s = cls[a * C + c];
            int b = (int)(s * (float)NBINS);
            b = max(0, min(NBINS - 1, b));
            if (b >= T && nk < 8) keys[nk++] = mkkey(s, (unsigned)a);
        }
        __syncthreads();
        for (int q = 0; q < nk; q++) {
            int p = atomicAdd(&sCnt, 1);
            if (p < NCAND) cand[p] = keys[q];
        }
        __syncthreads();
        n = min(sCnt, NCAND);
        for (int i = tid; i < NCAND; i += 1024)
            if (i >= n) cand[i] = 0ull;
        __syncthreads();
    }

    for (int k = 2; k <= NCAND; k <<= 1) {
        for (int j = k >> 1; j > 0; j >>= 1) {
            #pragma unroll
            for (int rep = 0; rep < 2; rep++) {
                int i = tid + rep * 1024;
                int ixj = i ^ j;
                if (ixj > i) {
                    unsigned long long a0 = cand[i], b0 = cand[ixj];
                    bool desc = ((i & k) == 0);
                    bool swap = desc ? (a0 < b0) : (a0 > b0);
                    if (swap) { cand[i] = b0; cand[ixj] = a0; }
                }
            }
            __syncthreads();
        }
    }

    bool alive = false;
    {
        unsigned long long v = cand[min(tid, NCAND - 1)];
        float s = fkey_inv((unsigned)(v >> 32));
        unsigned a = 0xFFFFFFFFu - (unsigned)(v & 0xFFFFFFFFull);
        bool valid = (a < (unsigned)A);
        float4 bb = valid ? g_boxes[min(a, (unsigned)(AMAX - 1))]
                          : make_float4(0.f, 0.f, 0.f, 0.f);
        if (!valid) s = 0.f;
        if (tid < KTOP) {
            int o = c * KTOP + tid;
            g_scoreK[o] = s;
            g_boxK[o]   = bb;
            g_areaK[o]  = (bb.z - bb.x) * (bb.w - bb.y);
            alive = (s > 0.001f);
        }
    }
    unsigned bal = __ballot_sync(0xFFFFFFFFu, alive);
    if ((tid & 63) == 0 && tid < KTOP + 63)
        salive[tid >> 6] = (unsigned long long)bal;
    __syncthreads();
    if ((tid & 63) == 32 && tid < KTOP + 63)
        atomicOr(&salive[tid >> 6], (unsigned long long)bal << 32);
    __syncthreads();
    if (tid < NWORDS) g_alive[c * NWORDS + tid] = salive[tid];
}

// ---------------------------------------------------------------------------
// Kernel 3: IoU suppression bitmask, flattened triangle for warp balance.
// Items t in [0, NITEMS) enumerate valid (wb, i): offStart(wb)=32*wb*(wb+1),
// i in [0, min(KTOP, wb*64+64)). 112 warps/class stride the items. Also
// records per-row nonzero bitmap for the sparse scan. IoU token-identical.
// ---------------------------------------------------------------------------
__global__ __launch_bounds__(512, 4)
void mask_kernel() {
    __shared__ float4 sbox[1024];
    __shared__ float  sarea[1024];
    int c = blockIdx.x, blk = blockIdx.y, tid = threadIdx.x;

    for (int i = tid; i < 1024; i += 512) {
        if (i < KTOP) {
            sbox[i]  = g_boxK[c * KTOP + i];
            sarea[i] = g_areaK[c * KTOP + i];
        } else {
            sbox[i]  = make_float4(3e8f, 3e8f, 3e8f, 3e8f);
            sarea[i] = 0.f;
        }
    }
    __syncthreads();

    int warp = tid >> 5, lane = tid & 31;
    int wg = blk * 16 + warp;                 // 0..111
    const int NW = 16 * MASK_BLOCKS;          // 112
    unsigned long long* mbase = g_mask + (size_t)c * KTOP * NWORDS;

    for (int t = wg; t < NITEMS; t += NW) {
        int wb = 15;
        #pragma unroll
        for (int k = 14; k >= 0; k--)
            if (t < 32 * (k + 1) * (k + 2)) wb = k;
        int i = t - 32 * wb * (wb + 1);

        int j1 = wb * 64 + lane;
        int j2 = j1 + 32;
        float4 B1 = sbox[j1], B2 = sbox[j2];
        float ar1 = sarea[j1], ar2 = sarea[j2];
        float4 BI = sbox[i];
        float  ai = sarea[i];

        float xx1 = fmaxf(BI.x, B1.x), yy1 = fmaxf(BI.y, B1.y);
        float xx2 = fminf(BI.z, B1.z), yy2 = fminf(BI.w, B1.w);
        float inter = fmaxf(xx2 - xx1, 0.f) * fmaxf(yy2 - yy1, 0.f);
        bool p1 = (j1 > i) && (inter > 0.5f * (ai + ar1 - inter + 1e-8f));
        xx1 = fmaxf(BI.x, B2.x); yy1 = fmaxf(BI.y, B2.y);
        xx2 = fminf(BI.z, B2.z); yy2 = fminf(BI.w, B2.w);
        inter = fmaxf(xx2 - xx1, 0.f) * fmaxf(yy2 - yy1, 0.f);
        bool p2 = (j2 > i) && (inter > 0.5f * (ai + ar2 - inter + 1e-8f));

        unsigned m1 = __ballot_sync(0xFFFFFFFFu, p1);
        unsigned m2 = __ballot_sync(0xFFFFFFFFu, p2);
        if (lane == 0) {
            unsigned long long word = ((unsigned long long)m2 << 32) | m1;
            mbase[(size_t)i * NWORDS + wb] = word;
            if (word)
                atomicOr(&g_rowNZ[c * NWORDS + (i >> 6)], 1ull << (i & 63));
        }
    }
}

// ---------------------------------------------------------------------------
// Kernel 4: sparse greedy scan over nonzero-row bitmap + output write.
// pending = cur[w] & nz[w]: all-zero rows are identity updates (exact skip);
// rows suppressed before their turn are cleared from cur before the ffs.
// Work scales with #nonzero rows (measured: suppression is rare).
// Clears g_cnt and g_rowNZ for the next replay.
// ---------------------------------------------------------------------------
__global__ __launch_bounds__(512)
void scan_kernel(float* __restrict__ out, int C) {
    __shared__ unsigned long long skeep[NWORDS];
    int c = blockIdx.x, tid = threadIdx.x;

    if (tid == 0) {
        const unsigned long long* __restrict__ mbase =
            g_mask + (size_t)c * KTOP * NWORDS;
        unsigned long long cur[NWORDS], nz[NWORDS];
        #pragma unroll
        for (int w = 0; w < NWORDS; w++) {
            cur[w] = g_alive[c * NWORDS + w];
            nz[w]  = g_rowNZ[c * NWORDS + w];
        }

        #pragma unroll
        for (int w = 0; w < NWORDS; w++) {
            unsigned long long pending = cur[w] & nz[w];
            while (pending) {
                int b = __ffsll((long long)pending) - 1;
                const ulonglong2* row2 = reinterpret_cast<const ulonglong2*>(
                    mbase + (size_t)(w * 64 + b) * NWORDS);
                #pragma unroll
                for (int p = (w >> 1); p < 8; p++) {
                    ulonglong2 r = row2[p];        // row word w has only bits > b
                    cur[2 * p]     &= ~r.x;        // (bit b survives)
                    cur[2 * p + 1] &= ~r.y;
                }
                pending = cur[w] & nz[w] & ((~1ull) << b);
            }
        }
        #pragma unroll
        for (int w = 0; w < NWORDS; w++) {
            skeep[w] = cur[w];
            g_rowNZ[c * NWORDS + w] = 0ull;        // reset for next replay
        }
        g_cnt[c] = 0;                               // reset for next replay
    }
    __syncthreads();

    float* out_scores = out;
    float* out_labels = out + (size_t)C * KTOP;
    float* out_boxes  = out + (size_t)2 * C * KTOP;
    float* out_keep   = out + (size_t)6 * C * KTOP;
    for (int i = tid; i < KTOP; i += 512) {
        bool kp = (skeep[i >> 6] >> (i & 63)) & 1ull;
        float kf = kp ? 1.0f : 0.0f;
        int o = c * KTOP + i;
        out_scores[o] = g_scoreK[o] * kf;
        out_labels[o] = (float)c;
        float4 bb = g_boxK[o];
        reinterpret_cast<float4*>(out_boxes)[o] =
            make_float4(bb.x * kf, bb.y * kf, bb.z * kf, bb.w * kf);
        out_keep[o] = kf;
    }
}

// ---------------------------------------------------------------------------
extern "C" void kernel_launch(void* const* d_in, const int* in_sizes, int n_in,
                              void* d_out, int out_size) {
    const float* cls  = (const float*)d_in[1];
    const float* reg  = (const float*)d_in[2];
    const float* anch = (const float*)d_in[3];

    int A = in_sizes[2] / 4;                    // 76725
    int C = in_sizes[1] / A;                    // 80
    int HW = in_sizes[0] / 3;                   // 640*640
    float H = floorf(sqrtf((float)HW) + 0.5f);  // 640

    long long gthreads = (long long)SEL_BLOCKS * DEC_THREADS;
    bool fast_ok = (C > 0) && ((C & 3) == 0) && (((A * (long long)C) & 3) == 0) &&
                   (((4 * gthreads) % C) == 0);
    int astep = fast_ok ? (int)((4 * gthreads) / C) : 0;
    int nblocks = DEC_BLOCKS + (fast_ok ? SEL_BLOCKS : 0);

    decode_select_kernel<<<nblocks, DEC_THREADS>>>(reg, anch, cls, A, C, H, H, astep);
    sort_kernel<<<C, 1024>>>(cls, A, C);
    mask_kernel<<<dim3(C, MASK_BLOCKS), 512>>>();
    scan_kernel<<<C, 512>>>((float*)d_out, C);
}

// round 17
// speedup vs baseline: 1.6366x; 1.6366x over previous
#include <cuda_runtime.h>
#include <math.h>

#define AMAX   76725
#define NCLS   80
#define KTOP   1000
#define NCAND  2048
#define NWORDS 16
#define NBINS  8192
#define THR_SEL 0.98f
#define NPH    37          // mask row-phases: 80*37=2960 blocks = 5 exact waves @4/SM

#define DEC_THREADS 320
#define DEC_BLOCKS  ((AMAX + DEC_THREADS - 1) / DEC_THREADS)   // 240
#define SEL_BLOCKS  1184

__device__ float4              g_boxes[AMAX];
__device__ unsigned long long  g_cand[NCLS * NCAND];
__device__ int                 g_cnt[NCLS];                    // zeroed at end of scan
__device__ float               g_scoreK[NCLS * KTOP];
__device__ float4              g_boxK[NCLS * KTOP];
__device__ float               g_areaK[NCLS * KTOP];
__device__ unsigned long long  g_alive[NCLS * NWORDS];
__device__ unsigned long long  g_mask[NCLS * KTOP * NWORDS];   // words wb<i>>6 never written/read
__device__ unsigned long long  g_rowNZ[NCLS * NWORDS];         // bit i: row i has a nonzero word

// ---------------------------------------------------------------------------
__device__ __forceinline__ unsigned fkey(float s) {
    unsigned b = __float_as_uint(s);
    return (b & 0x80000000u) ? ~b : (b | 0x80000000u);
}
__device__ __forceinline__ float fkey_inv(unsigned k) {
    return __uint_as_float((k & 0x80000000u) ? (k & 0x7FFFFFFFu) : ~k);
}
__device__ __forceinline__ unsigned long long mkkey(float s, unsigned a) {
    return ((unsigned long long)fkey(s) << 32) |
           (unsigned long long)(0xFFFFFFFFu - a);
}

// ---------------------------------------------------------------------------
// Kernel 1: fused decode (blocks [0, DEC_BLOCKS)) + select (rest).
// ---------------------------------------------------------------------------
__global__ __launch_bounds__(DEC_THREADS)
void decode_select_kernel(const float* __restrict__ reg,
                          const float* __restrict__ anch,
                          const float* __restrict__ cls,
                          int A, int C, float W, float H, int astep) {
    if (blockIdx.x < DEC_BLOCKS) {
        int a = blockIdx.x * DEC_THREADS + threadIdx.x;
        if (a >= A) return;
        float4 an = reinterpret_cast<const float4*>(anch)[a];
        float4 dl = reinterpret_cast<const float4*>(reg)[a];
        float aw = an.z - an.x;
        float ah = an.w - an.y;
        float cx = an.x + 0.5f * aw;
        float cy = an.y + 0.5f * ah;
        float pcx = cx + dl.x * 0.1f * aw;
        float pcy = cy + dl.y * 0.1f * ah;
        float pw = expf(dl.z * 0.2f) * aw;
        float ph = expf(dl.w * 0.2f) * ah;
        float4 b;
        b.x = fmaxf(pcx - 0.5f * pw, 0.0f);
        b.y = fmaxf(pcy - 0.5f * ph, 0.0f);
        b.z = fminf(pcx + 0.5f * pw, W);
        b.w = fminf(pcy + 0.5f * ph, H);
        g_boxes[a] = b;
        return;
    }
    // ---- select part ----
    int gthreads = SEL_BLOCKS * DEC_THREADS;
    int t = (blockIdx.x - DEC_BLOCKS) * DEC_THREADS + threadIdx.x;
    int nf4 = (A * C) >> 2;
    const float4* cls4 = reinterpret_cast<const float4*>(cls);
    int e0 = t << 2;
    int a  = e0 / C;
    int c0 = e0 - a * C;      // constant per thread across iterations
    for (int f = t; f < nf4; f += gthreads, a += astep) {
        float4 v = cls4[f];
        if (v.x > THR_SEL) {
            int p = atomicAdd(&g_cnt[c0 + 0], 1);
            if (p < NCAND) g_cand[(c0 + 0) * NCAND + p] = mkkey(v.x, (unsigned)a);
        }
        if (v.y > THR_SEL) {
            int p = atomicAdd(&g_cnt[c0 + 1], 1);
            if (p < NCAND) g_cand[(c0 + 1) * NCAND + p] = mkkey(v.y, (unsigned)a);
        }
        if (v.z > THR_SEL) {
            int p = atomicAdd(&g_cnt[c0 + 2], 1);
            if (p < NCAND) g_cand[(c0 + 2) * NCAND + p] = mkkey(v.z, (unsigned)a);
        }
        if (v.w > THR_SEL) {
            int p = atomicAdd(&g_cnt[c0 + 3], 1);
            if (p < NCAND) g_cand[(c0 + 3) * NCAND + p] = mkkey(v.w, (unsigned)a);
        }
    }
}

// ---------------------------------------------------------------------------
// Kernel 2: per-class sort (+embedded exact-reselect guard), extract top-K.
// ---------------------------------------------------------------------------
__global__ __launch_bounds__(1024)
void sort_kernel(const float* __restrict__ cls, int A, int C) {
    __shared__ unsigned long long buf[4096];       // 32 KB: cand = buf[0..2047]
    __shared__ unsigned long long salive[NWORDS];
    __shared__ int sT, sCnt;
    unsigned long long* cand = buf;
    unsigned*           hist = (unsigned*)buf;

    int c = blockIdx.x, tid = threadIdx.x;
    int n = g_cnt[c];
    bool bad = (n < KTOP) | (n > NCAND);

    if (!bad) {
        for (int i = tid; i < NCAND; i += 1024)
            cand[i] = (i < n) ? g_cand[c * NCAND + i] : 0ull;
        __syncthreads();
    } else {
        for (int i = tid; i < NBINS; i += 1024) hist[i] = 0u;
        if (tid == 0) sCnt = 0;
        __syncthreads();
        for (int a = tid; a < A; a += 1024) {
            float s = cls[a * C + c];
            int b = (int)(s * (float)NBINS);
            b = max(0, min(NBINS - 1, b));
            atomicAdd(&hist[b], 1u);
        }
        __syncthreads();
        if (tid == 0) {
            int cum = 0, t;
            for (t = NBINS - 1; t >= 0; t--) {
                cum += (int)hist[t];
                if (cum >= KTOP) break;
            }
            sT = (t < 0) ? 0 : t;
        }
        __syncthreads();
        int T = sT;
        unsigned long long keys[8]; int nk = 0;
        for (int a = tid; a < A; a += 1024) {
            float s = cls[a * C + c];
            int b = (int)(s * (float)NBINS);
            b = max(0, min(NBINS - 1, b));
            if (b >= T && nk < 8) keys[nk++] = mkkey(s, (unsigned)a);
        }
        __syncthreads();
        for (int q = 0; q < nk; q++) {
            int p = atomicAdd(&sCnt, 1);
            if (p < NCAND) cand[p] = keys[q];
        }
        __syncthreads();
        n = min(sCnt, NCAND);
        for (int i = tid; i < NCAND; i += 1024)
            if (i >= n) cand[i] = 0ull;
        __syncthreads();
    }

    for (int k = 2; k <= NCAND; k <<= 1) {
        for (int j = k >> 1; j > 0; j >>= 1) {
            #pragma unroll
            for (int rep = 0; rep < 2; rep++) {
                int i = tid + rep * 1024;
                int ixj = i ^ j;
                if (ixj > i) {
                    unsigned long long a0 = cand[i], b0 = cand[ixj];
                    bool desc = ((i & k) == 0);
                    bool swap = desc ? (a0 < b0) : (a0 > b0);
                    if (swap) { cand[i] = b0; cand[ixj] = a0; }
                }
            }
            __syncthreads();
        }
    }

    bool alive = false;
    {
        unsigned long long v = cand[min(tid, NCAND - 1)];
        float s = fkey_inv((unsigned)(v >> 32));
        unsigned a = 0xFFFFFFFFu - (unsigned)(v & 0xFFFFFFFFull);
        bool valid = (a < (unsigned)A);
        float4 bb = valid ? g_boxes[min(a, (unsigned)(AMAX - 1))]
                          : make_float4(0.f, 0.f, 0.f, 0.f);
        if (!valid) s = 0.f;
        if (tid < KTOP) {
            int o = c * KTOP + tid;
            g_scoreK[o] = s;
            g_boxK[o]   = bb;
            g_areaK[o]  = (bb.z - bb.x) * (bb.w - bb.y);
            alive = (s > 0.001f);
        }
    }
    unsigned bal = __ballot_sync(0xFFFFFFFFu, alive);
    if ((tid & 63) == 0 && tid < KTOP + 63)
        salive[tid >> 6] = (unsigned long long)bal;
    __syncthreads();
    if ((tid & 63) == 32 && tid < KTOP + 63)
        atomicOr(&salive[tid >> 6], (unsigned long long)bal << 32);
    __syncthreads();
    if (tid < NWORDS) g_alive[c * NWORDS + tid] = salive[tid];
}

// ---------------------------------------------------------------------------
// Kernel 3: IoU suppression bitmask (R12's proven config) + nonzero-row
// bitmap recording. IoU expressions token-identical.
// ---------------------------------------------------------------------------
__global__ __launch_bounds__(512, 4)
void mask_kernel() {
    __shared__ float4 sbox[1024];
    __shared__ float  sarea[1024];
    int c = blockIdx.x, ph = blockIdx.y, tid = threadIdx.x;

    for (int i = tid; i < 1024; i += 512) {
        if (i < KTOP) {
            sbox[i]  = g_boxK[c * KTOP + i];
            sarea[i] = g_areaK[c * KTOP + i];
        } else {
            sbox[i]  = make_float4(3e8f, 3e8f, 3e8f, 3e8f);
            sarea[i] = 0.f;
        }
    }
    __syncthreads();

    int warp = tid >> 5, lane = tid & 31;
    int wb = warp;
    int j1 = wb * 64 + lane;
    int j2 = j1 + 32;
    float4 B1 = sbox[j1], B2 = sbox[j2];
    float ar1 = sarea[j1], ar2 = sarea[j2];

    int iLim = wb * 64 + 64;
    if (iLim > KTOP) iLim = KTOP;
    unsigned long long* mrow = g_mask + (size_t)c * KTOP * NWORDS + wb;
    unsigned long long* nzc  = g_rowNZ + c * NWORDS;

    for (int i0 = 2 * ph; i0 < iLim; i0 += 2 * NPH) {
        {
            int i = i0;
            float4 BI = sbox[i];
            float  ai = sarea[i];
            float xx1 = fmaxf(BI.x, B1.x), yy1 = fmaxf(BI.y, B1.y);
            float xx2 = fminf(BI.z, B1.z), yy2 = fminf(BI.w, B1.w);
            float inter = fmaxf(xx2 - xx1, 0.f) * fmaxf(yy2 - yy1, 0.f);
            bool p1 = (j1 > i) && (inter > 0.5f * (ai + ar1 - inter + 1e-8f));
            xx1 = fmaxf(BI.x, B2.x); yy1 = fmaxf(BI.y, B2.y);
            xx2 = fminf(BI.z, B2.z); yy2 = fminf(BI.w, B2.w);
            inter = fmaxf(xx2 - xx1, 0.f) * fmaxf(yy2 - yy1, 0.f);
            bool p2 = (j2 > i) && (inter > 0.5f * (ai + ar2 - inter + 1e-8f));
            unsigned m1 = __ballot_sync(0xFFFFFFFFu, p1);
            unsigned m2 = __ballot_sync(0xFFFFFFFFu, p2);
            if (lane == 0) {
                unsigned long long word = ((unsigned long long)m2 << 32) | m1;
                mrow[(size_t)i * NWORDS] = word;
                if (word) atomicOr(&nzc[i >> 6], 1ull << (i & 63));
            }
        }
        if (i0 + 1 < iLim) {
            int i = i0 + 1;
            float4 BI = sbox[i];
            float  ai = sarea[i];
            float xx1 = fmaxf(BI.x, B1.x), yy1 = fmaxf(BI.y, B1.y);
            float xx2 = fminf(BI.z, B1.z), yy2 = fminf(BI.w, B1.w);
            float inter = fmaxf(xx2 - xx1, 0.f) * fmaxf(yy2 - yy1, 0.f);
            bool p1 = (j1 > i) && (inter > 0.5f * (ai + ar1 - inter + 1e-8f));
            xx1 = fmaxf(BI.x, B2.x); yy1 = fmaxf(BI.y, B2.y);
            xx2 = fminf(BI.z, B2.z); yy2 = fminf(BI.w, B2.w);
            inter = fmaxf(xx2 - xx1, 0.f) * fmaxf(yy2 - yy1, 0.f);
            bool p2 = (j2 > i) && (inter > 0.5f * (ai + ar2 - inter + 1e-8f));
            unsigned m1 = __ballot_sync(0xFFFFFFFFu, p1);
            unsigned m2 = __ballot_sync(0xFFFFFFFFu, p2);
            if (lane == 0) {
                unsigned long long word = ((unsigned long long)m2 << 32) | m1;
                mrow[(size_t)i * NWORDS] = word;
                if (word) atomicOr(&nzc[i >> 6], 1ull << (i & 63));
            }
        }
    }
}

// ---------------------------------------------------------------------------
// Kernel 4: nz-driven branchless serial scan over SMEM + output write.
// The walk iterates over set bits of nz[w] (loop-invariant, known up front:
// ffs chain and row addresses are independent of cur -> loads pipeline).
// Update cur &= ~(row & m) with m = alive(cur[w],b): suppressed rows give
// m=0 (identity), zero rows are skipped (identity) => exact same recurrence
// as the full sequential scan. Clears g_cnt/g_rowNZ for the next replay.
// ---------------------------------------------------------------------------
#define SCAN_SMEM (KTOP * NWORDS * 8)
__global__ __launch_bounds__(512)
void scan_kernel(float* __restrict__ out, int C) {
    extern __shared__ unsigned long long smask[];
    __shared__ unsigned long long skeep[NWORDS];
    int c = blockIdx.x, tid = threadIdx.x;

    const uint4* src = reinterpret_cast<const uint4*>(g_mask + (size_t)c * KTOP * NWORDS);
    uint4* dst = reinterpret_cast<uint4*>(smask);
    for (int i = tid; i < KTOP * NWORDS / 2; i += 512) dst[i] = src[i];
    __syncthreads();

    if (tid == 0) {
        unsigned long long cur[NWORDS];
        #pragma unroll
        for (int w = 0; w < NWORDS; w++) cur[w] = g_alive[c * NWORDS + w];

        #pragma unroll
        for (int w = 0; w < NWORDS; w++) {
            unsigned long long nzw = g_rowNZ[c * NWORDS + w];   // loop-invariant
            while (nzw) {
                int b = __ffsll((long long)nzw) - 1;
                nzw &= nzw - 1;
                // all-ones iff candidate i = w*64+b alive when reached
                unsigned long long m = 0ull - ((cur[w] >> b) & 1ull);
                const ulonglong2* row2 = reinterpret_cast<const ulonglong2*>(
                    smask + (size_t)(w * 64 + b) * NWORDS);
                #pragma unroll
                for (int p = (w >> 1); p < 8; p++) {
                    ulonglong2 r = row2[p];        // words < w are zero: harmless
                    cur[2 * p]     &= ~(r.x & m);  // row word w has only bits > b
                    cur[2 * p + 1] &= ~(r.y & m);  // (bit b itself survives)
                }
            }
        }
        #pragma unroll
        for (int w = 0; w < NWORDS; w++) {
            skeep[w] = cur[w];
            g_rowNZ[c * NWORDS + w] = 0ull;        // reset for next replay
        }
        g_cnt[c] = 0;                               // reset for next replay
    }
    __syncthreads();

    float* out_scores = out;
    float* out_labels = out + (size_t)C * KTOP;
    float* out_boxes  = out + (size_t)2 * C * KTOP;
    float* out_keep   = out + (size_t)6 * C * KTOP;
    for (int i = tid; i < KTOP; i += 512) {
        bool kp = (skeep[i >> 6] >> (i & 63)) & 1ull;
        float kf = kp ? 1.0f : 0.0f;
        int o = c * KTOP + i;
        out_scores[o] = g_scoreK[o] * kf;
        out_labels[o] = (float)c;
        float4 bb = g_boxK[o];
        reinterpret_cast<float4*>(out_boxes)[o] =
            make_float4(bb.x * kf, bb.y * kf, bb.z * kf, bb.w * kf);
        out_keep[o] = kf;
    }
}

// ---------------------------------------------------------------------------
extern "C" void kernel_launch(void* const* d_in, const int* in_sizes, int n_in,
                              void* d_out, int out_size) {
    const float* cls  = (const float*)d_in[1];
    const float* reg  = (const float*)d_in[2];
    const float* anch = (const float*)d_in[3];

    int A = in_sizes[2] / 4;                    // 76725
    int C = in_sizes[1] / A;                    // 80
    int HW = in_sizes[0] / 3;                   // 640*640
    float H = floorf(sqrtf((float)HW) + 0.5f);  // 640

    long long gthreads = (long long)SEL_BLOCKS * DEC_THREADS;
    bool fast_ok = (C > 0) && ((C & 3) == 0) && (((A * (long long)C) & 3) == 0) &&
                   (((4 * gthreads) % C) == 0);
    int astep = fast_ok ? (int)((4 * gthreads) / C) : 0;
    int nblocks = DEC_BLOCKS + (fast_ok ? SEL_BLOCKS : 0);

    decode_select_kernel<<<nblocks, DEC_THREADS>>>(reg, anch, cls, A, C, H, H, astep);
    sort_kernel<<<C, 1024>>>(cls, A, C);
    mask_kernel<<<dim3(C, NPH), 512>>>();

    cudaFuncSetAttribute(scan_kernel,
                         cudaFuncAttributeMaxDynamicSharedMemorySize, SCAN_SMEM);
    scan_kernel<<<C, 512, SCAN_SMEM>>>((float*)d_out, C);
}